// round 17
// baseline (speedup 1.0000x reference)
#include <cuda_runtime.h>
#include <cuda_fp16.h>
#include <math.h>

// Problem constants (fixed by the reference)
constexpr int NN  = 100000;
constexpr int NN1 = 60000;
constexpr int NN2 = 30000;
constexpr int EE  = 1600000;
constexpr int DIN = 128;
constexpr int HH  = 64;

// ---------------- float scratch ----------------
constexpr long long F_HMASK = 0;
constexpr long long F_HNEI1 = F_HMASK + (long long)NN * HH;          // fp16: NN1*HH/2 floats
constexpr long long F_HNEI2 = F_HNEI1 + (long long)NN1 * HH / 2;
constexpr long long F_SUM1  = F_HNEI2 + (long long)NN2 * HH / 2;
constexpr long long F_SUM2  = F_SUM1 + (long long)NN * HH;
constexpr long long F_TOTAL = F_SUM2 + (long long)NN * HH;

__device__ float g_fscratch[F_TOTAL];

// ---------------- int scratch ----------------
constexpr long long I_DEG1 = 0;
constexpr long long I_DEG2 = I_DEG1 + NN;
constexpr long long I_ROW1 = I_DEG2 + NN;
constexpr long long I_ROW2 = I_ROW1 + NN;
constexpr long long I_CUR1 = I_ROW2 + NN;
constexpr long long I_CUR2 = I_CUR1 + NN;
constexpr long long I_CTR  = I_CUR2 + NN;
constexpr long long I_EDST1 = I_CTR + 32;
constexpr long long I_EDST2 = I_EDST1 + EE;
constexpr long long I_TOTAL = I_EDST2 + EE;

__device__ int g_iscratch[I_TOTAL];

// ---------------- helpers ----------------
__device__ __forceinline__ float elu1(float x) { return x > 0.f ? x : expm1f(x); }
__device__ __forceinline__ float4 elu4(float4 v) {
    v.x = elu1(v.x); v.y = elu1(v.y); v.z = elu1(v.z); v.w = elu1(v.w);
    return v;
}

// Packed f32x2 ops (Blackwell): FFMA2 = 2 fp32 FLOP per lane per issue.
__device__ __forceinline__ unsigned long long pk2(float x) {
    unsigned long long r;
    asm("mov.b64 %0, {%1, %1};" : "=l"(r) : "f"(x));
    return r;
}
__device__ __forceinline__ unsigned long long fma2(unsigned long long a,
                                                   unsigned long long b,
                                                   unsigned long long c) {
    unsigned long long d;
    asm("fma.rn.f32x2 %0, %1, %2, %3;" : "=l"(d) : "l"(a), "l"(b), "l"(c));
    return d;
}
__device__ __forceinline__ void unpk2(unsigned long long v, float& lo, float& hi) {
    asm("mov.b64 {%0, %1}, %2;" : "=f"(lo), "=f"(hi) : "l"(v));
}

// ================= input GEMM: Y = elu(X[r,:128] @ W[:,64] + b) =================
// 64x64 tile, 128 threads, 8 rows x 4 cols (2 col-pairs) per thread, f32x2 FMA.
template<bool HALF_OUT>
__global__ __launch_bounds__(128)
void gemm64_kernel(const float* __restrict__ X, const float* __restrict__ W,
                   const float* __restrict__ b, void* __restrict__ Yv, int rows)
{
    constexpr int K4 = DIN / 4;          // 32
    __shared__ float4 Xs[64 * K4];       // 32KB
    __shared__ float4 Wp[32 * 64];       // 32KB  (col-pair x k2)

    const int t = threadIdx.x;
    const int rowBase = blockIdx.x * 64;

    const float4* X4 = (const float4*)X;
#pragma unroll
    for (int it = 0; it < 16; it++) {
        int idx = t + it * 128;          // [0, 2048)
        int r  = idx >> 5;
        int k4 = idx & 31;
        int gr = rowBase + r;
        float4 v = make_float4(0.f, 0.f, 0.f, 0.f);
        if (gr < rows) v = X4[(long long)gr * K4 + k4];
        Xs[idx] = v;
    }
    // W [128][64] -> Wp pair-interleaved with swizzle
    float* Wf = (float*)Wp;
#pragma unroll
    for (int it = 0; it < 64; it++) {
        int idx = t + it * 128;          // [0, 8192)
        int k = idx >> 6;                // 0..127
        int c = idx & 63;                // 0..63
        int c2 = c >> 1;                 // col pair 0..31
        int k2 = k >> 1;                 // k pair 0..63
        int k2s = k2 ^ ((c2 >> 1) & 15);
        Wf[(c2 * 64 + k2s) * 4 + (k & 1) * 2 + (c & 1)] = W[idx];
    }
    __syncthreads();

    const int c4 = t & 15;               // output float4 column group
    const int r0 = (t >> 4) * 8;         // 8 rows per thread
    const int swz = c4;                  // = cc>>1 for cc in {2c4, 2c4+1}

    unsigned long long acc2[8][2];
#pragma unroll
    for (int i = 0; i < 8; i++) { acc2[i][0] = 0ull; acc2[i][1] = 0ull; }

#pragma unroll 4
    for (int k4 = 0; k4 < K4; k4++) {
        const int cc0 = 2 * c4, cc1 = 2 * c4 + 1;
        float4 w00 = Wp[cc0 * 64 + ((2 * k4)     ^ swz)];
        float4 w01 = Wp[cc0 * 64 + ((2 * k4 + 1) ^ swz)];
        float4 w10 = Wp[cc1 * 64 + ((2 * k4)     ^ swz)];
        float4 w11 = Wp[cc1 * 64 + ((2 * k4 + 1) ^ swz)];
        unsigned long long w00lo = ((unsigned long long*)&w00)[0];
        unsigned long long w00hi = ((unsigned long long*)&w00)[1];
        unsigned long long w01lo = ((unsigned long long*)&w01)[0];
        unsigned long long w01hi = ((unsigned long long*)&w01)[1];
        unsigned long long w10lo = ((unsigned long long*)&w10)[0];
        unsigned long long w10hi = ((unsigned long long*)&w10)[1];
        unsigned long long w11lo = ((unsigned long long*)&w11)[0];
        unsigned long long w11hi = ((unsigned long long*)&w11)[1];

#pragma unroll
        for (int i = 0; i < 8; i++) {
            float4 x = Xs[(r0 + i) * K4 + k4];
            unsigned long long px0 = pk2(x.x);
            unsigned long long px1 = pk2(x.y);
            unsigned long long px2 = pk2(x.z);
            unsigned long long px3 = pk2(x.w);
            acc2[i][0] = fma2(px0, w00lo, acc2[i][0]);
            acc2[i][1] = fma2(px0, w10lo, acc2[i][1]);
            acc2[i][0] = fma2(px1, w00hi, acc2[i][0]);
            acc2[i][1] = fma2(px1, w10hi, acc2[i][1]);
            acc2[i][0] = fma2(px2, w01lo, acc2[i][0]);
            acc2[i][1] = fma2(px2, w11lo, acc2[i][1]);
            acc2[i][0] = fma2(px3, w01hi, acc2[i][0]);
            acc2[i][1] = fma2(px3, w11hi, acc2[i][1]);
        }
    }

    float4 bias = ((const float4*)b)[c4];
#pragma unroll
    for (int i = 0; i < 8; i++) {
        int gr = rowBase + r0 + i;
        if (gr < rows) {
            float4 o;
            unpk2(acc2[i][0], o.x, o.y);
            unpk2(acc2[i][1], o.z, o.w);
            o.x += bias.x; o.y += bias.y; o.z += bias.z; o.w += bias.w;
            o = elu4(o);
            if (HALF_OUT) {
                __half2 h0 = __floats2half2_rn(o.x, o.y);
                __half2 h1 = __floats2half2_rn(o.z, o.w);
                uint2 pkv;
                pkv.x = *(unsigned*)&h0;
                pkv.y = *(unsigned*)&h1;
                ((uint2*)Yv)[(long long)gr * 16 + c4] = pkv;
            } else {
                ((float4*)Yv)[(long long)gr * 16 + c4] = o;
            }
        }
    }
}

// ================= CSR build (proven versions) =================
__global__ __launch_bounds__(256)
void zero_kernel(int* __restrict__ d1, int* __restrict__ d2, int* __restrict__ ctr)
{
    int i = blockIdx.x * 256 + threadIdx.x;
    if (i < NN) { d1[i] = 0; d2[i] = 0; }
    if (i < 2) ctr[i] = 0;
}

__global__ __launch_bounds__(256)
void hist2_kernel(const int* __restrict__ src1, const int* __restrict__ src2,
                  int* __restrict__ deg1, int* __restrict__ deg2)
{
    int e = blockIdx.x * 256 + threadIdx.x;
    if (e < EE)            atomicAdd(deg1 + __ldg(src1 + e), 1);
    else if (e < 2 * EE)   atomicAdd(deg2 + __ldg(src2 + e - EE), 1);
}

__global__ __launch_bounds__(256)
void base2_kernel(const int* __restrict__ deg1, int* __restrict__ row1, int* __restrict__ cur1,
                  const int* __restrict__ deg2, int* __restrict__ row2, int* __restrict__ cur2,
                  int* __restrict__ ctr, int nb)
{
    __shared__ int warpTot[8];
    __shared__ int blockBase;
    int rel = blockIdx.x >= nb;
    const int* deg = rel ? deg2 : deg1;
    int* rowp = rel ? row2 : row1;
    int* cur  = rel ? cur2 : cur1;
    int* counter = ctr + rel;

    int i = (blockIdx.x - rel * nb) * 256 + threadIdx.x;
    int lane = threadIdx.x & 31;
    int wid  = threadIdx.x >> 5;

    int d = (i < NN) ? deg[i] : 0;
    int x = d;
#pragma unroll
    for (int o = 1; o < 32; o <<= 1) {
        int y = __shfl_up_sync(0xffffffffu, x, o);
        if (lane >= o) x += y;
    }
    if (lane == 31) warpTot[wid] = x;
    __syncthreads();
    if (threadIdx.x == 0) {
        int s = 0;
#pragma unroll
        for (int w = 0; w < 8; w++) { int tw = warpTot[w]; warpTot[w] = s; s += tw; }
        blockBase = atomicAdd(counter, s);
    }
    __syncthreads();
    int base = blockBase + warpTot[wid] + x - d;
    if (i < NN) { rowp[i] = base; cur[i] = base; }
}

__global__ __launch_bounds__(256)
void reorder2_kernel(const int* __restrict__ src1, const int* __restrict__ dst1,
                     int* __restrict__ cur1, int* __restrict__ edst1,
                     const int* __restrict__ src2, const int* __restrict__ dst2,
                     int* __restrict__ cur2, int* __restrict__ edst2)
{
    int e = blockIdx.x * 256 + threadIdx.x;
    if (e < EE) {
        int s = __ldg(src1 + e);
        int pos = atomicAdd(cur1 + s, 1);
        edst1[pos] = __ldg(dst1 + e);
    } else if (e < 2 * EE) {
        e -= EE;
        int s = __ldg(src2 + e);
        int pos = atomicAdd(cur2 + s, 1);
        edst2[pos] = __ldg(dst2 + e);
    }
}

// ================= aggregate: one warp per node, fp16 rows, MLP=8 =========
__global__ __launch_bounds__(256)
void agg_kernel(const int* __restrict__ rowptr, const int* __restrict__ deg,
                const int* __restrict__ edst, const __half2* __restrict__ hnei,
                float2* __restrict__ sum, int n)
{
    int warp = (blockIdx.x * 256 + threadIdx.x) >> 5;
    int lane = threadIdx.x & 31;
    if (warp >= n) return;

    int base = __ldg(rowptr + warp);
    int d    = __ldg(deg + warp);

    float2 acc = make_float2(0.f, 0.f);
    for (int j0 = 0; j0 < d; j0 += 32) {
        int e = 0;
        if (j0 + lane < d) e = __ldg(edst + base + j0 + lane);
        int m = min(32, d - j0);
        int jj = 0;
        for (; jj + 8 <= m; jj += 8) {
            int i0 = __shfl_sync(0xffffffffu, e, jj);
            int i1 = __shfl_sync(0xffffffffu, e, jj + 1);
            int i2 = __shfl_sync(0xffffffffu, e, jj + 2);
            int i3 = __shfl_sync(0xffffffffu, e, jj + 3);
            int i4 = __shfl_sync(0xffffffffu, e, jj + 4);
            int i5 = __shfl_sync(0xffffffffu, e, jj + 5);
            int i6 = __shfl_sync(0xffffffffu, e, jj + 6);
            int i7 = __shfl_sync(0xffffffffu, e, jj + 7);
            float2 v0 = __half22float2(__ldg(hnei + (long long)i0 * 32 + lane));
            float2 v1 = __half22float2(__ldg(hnei + (long long)i1 * 32 + lane));
            float2 v2 = __half22float2(__ldg(hnei + (long long)i2 * 32 + lane));
            float2 v3 = __half22float2(__ldg(hnei + (long long)i3 * 32 + lane));
            float2 v4 = __half22float2(__ldg(hnei + (long long)i4 * 32 + lane));
            float2 v5 = __half22float2(__ldg(hnei + (long long)i5 * 32 + lane));
            float2 v6 = __half22float2(__ldg(hnei + (long long)i6 * 32 + lane));
            float2 v7 = __half22float2(__ldg(hnei + (long long)i7 * 32 + lane));
            acc.x += (v0.x + v1.x) + (v2.x + v3.x) + (v4.x + v5.x) + (v6.x + v7.x);
            acc.y += (v0.y + v1.y) + (v2.y + v3.y) + (v4.y + v5.y) + (v6.y + v7.y);
        }
        for (; jj + 4 <= m; jj += 4) {
            int i0 = __shfl_sync(0xffffffffu, e, jj);
            int i1 = __shfl_sync(0xffffffffu, e, jj + 1);
            int i2 = __shfl_sync(0xffffffffu, e, jj + 2);
            int i3 = __shfl_sync(0xffffffffu, e, jj + 3);
            float2 v0 = __half22float2(__ldg(hnei + (long long)i0 * 32 + lane));
            float2 v1 = __half22float2(__ldg(hnei + (long long)i1 * 32 + lane));
            float2 v2 = __half22float2(__ldg(hnei + (long long)i2 * 32 + lane));
            float2 v3 = __half22float2(__ldg(hnei + (long long)i3 * 32 + lane));
            acc.x += (v0.x + v1.x) + (v2.x + v3.x);
            acc.y += (v0.y + v1.y) + (v2.y + v3.y);
        }
        for (; jj < m; jj++) {
            int dd = __shfl_sync(0xffffffffu, e, jj);
            float2 v = __half22float2(__ldg(hnei + (long long)dd * 32 + lane));
            acc.x += v.x;
            acc.y += v.y;
        }
    }
    sum[(long long)warp * 32 + lane] = acc;
}

// ================= fused A-GEMM x2 + epilogue, f32x2 inner loops ==============
// acc1 = sum1_tile @ A0 ; acc2 = sum2_tile @ A1  (64x64 tile, 4 rows x 2 col-pairs)
__global__ __launch_bounds__(256)
void gemm_epi_kernel(const float* __restrict__ sum1, const float* __restrict__ A0,
                     const float* __restrict__ sum2, const float* __restrict__ A1,
                     const int* __restrict__ deg1, const int* __restrict__ deg2,
                     const float4* __restrict__ hmask, float* __restrict__ out)
{
    constexpr int K4 = HH / 4;           // 16
    __shared__ float4 Xs[64 * K4];       // 16KB
    __shared__ float4 Wp[32 * 32];       // 16KB (col-pair x k2)

    const int t = threadIdx.x;
    const int rowBase = blockIdx.x * 64;
    const int c4  = t & 15;
    const int r0  = (t >> 4) * 4;
    const int swz = c4;                  // = c2>>1 for c2 in {2c4, 2c4+1}

    unsigned long long a1p[4][2], a2p[4][2];

    for (int phase = 0; phase < 2; phase++) {
        const float4* X4 = phase ? (const float4*)sum2 : (const float4*)sum1;
        const float* W   = phase ? A1 : A0;
        if (phase) __syncthreads();      // all reads of phase-0 tiles done

#pragma unroll
        for (int it = 0; it < 4; it++) {
            int idx = t + it * 256;      // [0, 1024)
            int r  = idx >> 4;
            int k4 = idx & 15;
            int gr = rowBase + r;
            float4 v = make_float4(0.f, 0.f, 0.f, 0.f);
            if (gr < NN) v = X4[(long long)gr * K4 + k4];
            Xs[idx] = v;
        }
        // W [64][64] -> Wp pair-interleaved with swizzle
        float* Wf = (float*)Wp;
#pragma unroll
        for (int it = 0; it < 16; it++) {
            int idx = t + it * 256;      // [0, 4096)
            int k = idx >> 6;            // 0..63
            int c = idx & 63;            // 0..63
            int c2 = c >> 1;             // 0..31
            int k2 = k >> 1;             // 0..31
            int k2s = k2 ^ ((c2 >> 1) & 31);
            Wf[(c2 * 32 + k2s) * 4 + (k & 1) * 2 + (c & 1)] = W[idx];
        }
        __syncthreads();

        unsigned long long (*acc)[2] = phase ? a2p : a1p;
#pragma unroll
        for (int i = 0; i < 4; i++) { acc[i][0] = 0ull; acc[i][1] = 0ull; }

#pragma unroll 4
        for (int k4 = 0; k4 < K4; k4++) {
            const int cc0 = 2 * c4, cc1 = 2 * c4 + 1;
            float4 w00 = Wp[cc0 * 32 + ((2 * k4)     ^ swz)];
            float4 w01 = Wp[cc0 * 32 + ((2 * k4 + 1) ^ swz)];
            float4 w10 = Wp[cc1 * 32 + ((2 * k4)     ^ swz)];
            float4 w11 = Wp[cc1 * 32 + ((2 * k4 + 1) ^ swz)];
            unsigned long long w00lo = ((unsigned long long*)&w00)[0];
            unsigned long long w00hi = ((unsigned long long*)&w00)[1];
            unsigned long long w01lo = ((unsigned long long*)&w01)[0];
            unsigned long long w01hi = ((unsigned long long*)&w01)[1];
            unsigned long long w10lo = ((unsigned long long*)&w10)[0];
            unsigned long long w10hi = ((unsigned long long*)&w10)[1];
            unsigned long long w11lo = ((unsigned long long*)&w11)[0];
            unsigned long long w11hi = ((unsigned long long*)&w11)[1];

#pragma unroll
            for (int i = 0; i < 4; i++) {
                float4 x = Xs[(r0 + i) * K4 + k4];
                unsigned long long px0 = pk2(x.x);
                unsigned long long px1 = pk2(x.y);
                unsigned long long px2 = pk2(x.z);
                unsigned long long px3 = pk2(x.w);
                acc[i][0] = fma2(px0, w00lo, acc[i][0]);
                acc[i][1] = fma2(px0, w10lo, acc[i][1]);
                acc[i][0] = fma2(px1, w00hi, acc[i][0]);
                acc[i][1] = fma2(px1, w10hi, acc[i][1]);
                acc[i][0] = fma2(px2, w01lo, acc[i][0]);
                acc[i][1] = fma2(px2, w11lo, acc[i][1]);
                acc[i][0] = fma2(px3, w01hi, acc[i][0]);
                acc[i][1] = fma2(px3, w11hi, acc[i][1]);
            }
        }
    }

    // epilogue
    float4* O = (float4*)out;
    const float4* HT = O + 4LL * NN * 16;
#pragma unroll
    for (int i = 0; i < 4; i++) {
        int gr = rowBase + r0 + i;
        if (gr >= NN) continue;
        int d1 = __ldg(deg1 + gr);
        int d2 = __ldg(deg2 + gr);
        float inv1 = d1 > 0 ? 1.f / (float)d1 : 1.f;
        float inv2 = d2 > 0 ? 1.f / (float)d2 : 1.f;
        float4 a1, a2;
        unpk2(a1p[i][0], a1.x, a1.y);
        unpk2(a1p[i][1], a1.z, a1.w);
        unpk2(a2p[i][0], a2.x, a2.y);
        unpk2(a2p[i][1], a2.z, a2.w);
        a1.x *= inv1; a1.y *= inv1; a1.z *= inv1; a1.w *= inv1;
        a2.x *= inv2; a2.y *= inv2; a2.z *= inv2; a2.w *= inv2;
        long long g = (long long)gr * 16 + c4;
        float4 ht = HT[g];
        float4 hm = hmask[g];
        float4 v;
        v = make_float4(ht.x + a1.x, ht.y + a1.y, ht.z + a1.z, ht.w + a1.w);
        O[0LL * NN * 16 + g] = elu4(v);
        v = make_float4(hm.x + a1.x, hm.y + a1.y, hm.z + a1.z, hm.w + a1.w);
        O[1LL * NN * 16 + g] = elu4(v);
        v = make_float4(ht.x + a2.x, ht.y + a2.y, ht.z + a2.z, ht.w + a2.w);
        O[2LL * NN * 16 + g] = elu4(v);
        v = make_float4(hm.x + a2.x, hm.y + a2.y, hm.z + a2.z, hm.w + a2.w);
        O[3LL * NN * 16 + g] = elu4(v);
    }
}

// ================= launch (single stream, no statics, no attribute calls) =========
extern "C" void kernel_launch(void* const* d_in, const int* in_sizes, int n_in,
                              void* d_out, int out_size)
{
    const float* feats0    = (const float*)d_in[0];
    const float* feats1    = (const float*)d_in[1];
    const float* feats2    = (const float*)d_in[2];
    const float* mask_feat = (const float*)d_in[3];
    const int*   src1      = (const int*)d_in[4];
    const int*   dst1      = (const int*)d_in[5];
    const int*   src2      = (const int*)d_in[6];
    const int*   dst2      = (const int*)d_in[7];
    const float* W0        = (const float*)d_in[8];
    const float* b0        = (const float*)d_in[9];
    const float* W1        = (const float*)d_in[10];
    const float* b1        = (const float*)d_in[11];
    const float* W2        = (const float*)d_in[12];
    const float* b2        = (const float*)d_in[13];
    const float* A0        = (const float*)d_in[14];
    const float* A1        = (const float*)d_in[15];

    float* out = (float*)d_out;

    void* fp = nullptr; cudaGetSymbolAddress(&fp, g_fscratch);
    void* ip = nullptr; cudaGetSymbolAddress(&ip, g_iscratch);
    float* F = (float*)fp;
    int*   I = (int*)ip;

    float*   hmask = F + F_HMASK;
    __half*  hnei1 = (__half*)(F + F_HNEI1);
    __half*  hnei2 = (__half*)(F + F_HNEI2);
    float*   sum1  = F + F_SUM1;
    float*   sum2  = F + F_SUM2;

    int* deg1 = I + I_DEG1;
    int* deg2 = I + I_DEG2;
    int* row1 = I + I_ROW1;
    int* row2 = I + I_ROW2;
    int* cur1 = I + I_CUR1;
    int* cur2 = I + I_CUR2;
    int* ctr  = I + I_CTR;
    int* edst1 = I + I_EDST1;
    int* edst2 = I + I_EDST2;

    float* htar = out + 4LL * NN * HH;

    auto cdiv = [](long long a, long long b) { return (int)((a + b - 1) / b); };

    const int NB = cdiv(NN, 256);

    // CSR build chain
    zero_kernel<<<NB, 256>>>(deg1, deg2, ctr);
    hist2_kernel<<<cdiv(2LL * EE, 256), 256>>>(src1, src2, deg1, deg2);
    base2_kernel<<<2 * NB, 256>>>(deg1, row1, cur1, deg2, row2, cur2, ctr, NB);
    reorder2_kernel<<<cdiv(2LL * EE, 256), 256>>>(src1, dst1, cur1, edst1,
                                                  src2, dst2, cur2, edst2);

    // Input GEMMs (+bias +ELU) — f32x2 packed dual-FMA inner loop
    gemm64_kernel<true ><<<cdiv(NN1, 64), 128>>>(feats1,    W1, b1, hnei1, NN1);
    gemm64_kernel<true ><<<cdiv(NN2, 64), 128>>>(feats2,    W2, b2, hnei2, NN2);
    gemm64_kernel<false><<<cdiv(NN,  64), 128>>>(feats0,    W0, b0, htar,  NN);
    gemm64_kernel<false><<<cdiv(NN,  64), 128>>>(mask_feat, W0, b0, hmask, NN);

    // Gather-aggregate (fp16 rows, fp32 accumulation, MLP=8)
    agg_kernel<<<cdiv((long long)NN * 32, 256), 256>>>(row1, deg1, edst1,
                                                       (const __half2*)hnei1, (float2*)sum1, NN);
    agg_kernel<<<cdiv((long long)NN * 32, 256), 256>>>(row2, deg2, edst2,
                                                       (const __half2*)hnei2, (float2*)sum2, NN);

    // Fused A-GEMM x2 + epilogue — f32x2 inner loops
    gemm_epi_kernel<<<cdiv(NN, 64), 256>>>(sum1, A0, sum2, A1, deg1, deg2,
                                           (const float4*)hmask, out);
}